// round 17
// baseline (speedup 1.0000x reference)
#include <cuda_runtime.h>
#include <cuda_fp16.h>
#include <math.h>
#include <stdint.h>

// Problem constants
#define T_TOK   2048
#define D_MODEL 1024
#define N_EXP   8
#define HIDDEN  4096
#define TOPK    2
#define CAP     2048

// ---------------- scratch (device globals; no dynamic allocation) ----------
__device__ int    g_counts[N_EXP];
__device__ int    g_tok_expert[T_TOK * TOPK];
__device__ int    g_tok_slot[T_TOK * TOPK];
__device__ int    g_slot_tok[N_EXP * CAP];          // slot -> 2*token + choice
__device__ float  g_tok_weight[T_TOK * TOPK];
__device__ __align__(16) __half g_xg[(size_t)N_EXP * CAP * D_MODEL];  // 32 MB
__device__ __align__(16) __half g_h [(size_t)N_EXP * CAP * HIDDEN];   // 128 MB
__device__ __align__(16) float  g_eo[(size_t)N_EXP * CAP * D_MODEL];  // scratch (prewarm)

// ---------------- kernel 0: zero counters ----------------------------------
__global__ void zero_counts_kernel() {
    if (threadIdx.x < N_EXP) g_counts[threadIdx.x] = 0;
}

__device__ __forceinline__ uint32_t pack_h2(float x, float y) {
    __half2 h = __floats2half2_rn(x, y);
    return *(uint32_t*)&h;
}
__device__ __forceinline__ uint32_t smem_u32(const void* p) {
    uint32_t a;
    asm("{ .reg .u64 t; cvta.to.shared.u64 t, %1; cvt.u32.u64 %0, t; }" : "=r"(a) : "l"(p));
    return a;
}
__device__ __forceinline__ void ldm_x4(uint32_t* r, uint32_t addr) {
    asm volatile("ldmatrix.sync.aligned.m8n8.x4.shared.b16 {%0,%1,%2,%3}, [%4];"
        : "=r"(r[0]), "=r"(r[1]), "=r"(r[2]), "=r"(r[3]) : "r"(addr));
}

// ---------------- kernel 1: routing (R12-proven core) ----------------------
// Additions: records slot->token inverse map; zeroes this token's out row
// (out will be accumulated into by fc2's fused epilogue).
__global__ void routing_kernel(const float* __restrict__ x,
                               const float* __restrict__ gate_w,
                               float* __restrict__ out) {
    int t = blockIdx.x, tid = threadIdx.x, w = tid >> 5, lane = tid & 31;
    const float* xt = x + (size_t)t * D_MODEL;
    const float* gw = gate_w + (size_t)w * D_MODEL;
    float s = 0.f;
    #pragma unroll 4
    for (int k = lane; k < D_MODEL; k += 32) s += xt[k] * gw[k];
    #pragma unroll
    for (int off = 16; off; off >>= 1) s += __shfl_xor_sync(0xffffffffu, s, off);

    __shared__ float logits[N_EXP];
    __shared__ int   sh_e[TOPK];
    __shared__ int   sh_s[TOPK];
    if (lane == 0) logits[w] = s;
    __syncthreads();

    if (tid == 0) {
        float mx = logits[0];
        #pragma unroll
        for (int i = 1; i < N_EXP; i++) mx = fmaxf(mx, logits[i]);
        float denom = 0.f;
        #pragma unroll
        for (int i = 0; i < N_EXP; i++) denom += expf(logits[i] - mx);
        // top-2 scan; strict '>' keeps lower index on ties (matches jax top_k)
        float v0 = -3.4e38f, v1 = -3.4e38f;
        int   i0 = 0,        i1 = 0;
        #pragma unroll
        for (int i = 0; i < N_EXP; i++) {
            float v = logits[i];
            if (v > v0)      { v1 = v0; i1 = i0; v0 = v; i0 = i; }
            else if (v > v1) { v1 = v;  i1 = i; }
        }
        float p0 = expf(v0 - mx) / denom;
        float p1 = expf(v1 - mx) / denom;
        float inv = 1.f / (p0 + p1);
        p0 *= inv; p1 *= inv;
        int s0 = atomicAdd(&g_counts[i0], 1);
        int s1 = atomicAdd(&g_counts[i1], 1);
        g_tok_expert[t * 2 + 0] = i0;  g_tok_slot[t * 2 + 0] = s0;  g_tok_weight[t * 2 + 0] = p0;
        g_tok_expert[t * 2 + 1] = i1;  g_tok_slot[t * 2 + 1] = s1;  g_tok_weight[t * 2 + 1] = p1;
        g_slot_tok[i0 * CAP + s0] = t * 2 + 0;
        g_slot_tok[i1 * CAP + s1] = t * 2 + 1;
        sh_e[0] = i0; sh_s[0] = s0; sh_e[1] = i1; sh_s[1] = s1;
    }
    __syncthreads();

    // zero this token's output row (fc2 accumulates into it atomically)
    ((float4*)(out + (size_t)t * D_MODEL))[tid] = make_float4(0.f, 0.f, 0.f, 0.f);

    // gather token row (fp32 -> fp16) into both experts' input buffers
    float4 v = ((const float4*)xt)[tid];
    uint2 hv = make_uint2(pack_h2(v.x, v.y), pack_h2(v.z, v.w));
    #pragma unroll
    for (int kk = 0; kk < TOPK; kk++) {
        uint2* dst = (uint2*)(g_xg + ((size_t)sh_e[kk] * CAP + sh_s[kk]) * D_MODEL);
        dst[tid] = hv;
    }
}

// ---------------- fp16 tensor-core grouped NT GEMM (R12 core, proven) ------
// C[m,n] = sum_k A[m,k]*B[n,k] + bias[n]  (optional ReLU)
// FUSE_OUT=true (fc2): instead of storing C, look up this row's (token,
// weight) and atomicAdd w*(acc+bias) into out[token]. The two expert
// contributions per element are a 2-addend fp32 sum -> commutative ->
// bit-deterministic regardless of atomic order.

#define BM 128
#define BN 128
#define BK 32
#define BKH 40   // half stride (80 B)

__device__ __forceinline__ void mma_f16(float* c, const uint32_t* a, const uint32_t* b) {
    asm volatile(
        "mma.sync.aligned.m16n8k16.row.col.f32.f16.f16.f32 "
        "{%0,%1,%2,%3}, {%4,%5,%6,%7}, {%8,%9}, {%0,%1,%2,%3};"
        : "+f"(c[0]), "+f"(c[1]), "+f"(c[2]), "+f"(c[3])
        : "r"(a[0]), "r"(a[1]), "r"(a[2]), "r"(a[3]), "r"(b[0]), "r"(b[1]));
}

template<bool RELU, typename OutT, bool FUSE_OUT>
__global__ __launch_bounds__(256)
void gemm_tc_kernel(const __half* __restrict__ Ab, const float* __restrict__ Bb,
                    const float* __restrict__ biasb, OutT* __restrict__ Cb,
                    int K, int N) {
    const int e  = blockIdx.z;
    const int M  = g_counts[e];
    const int m0 = blockIdx.x * BM;          // m fastest: wave shares B tile in L2
    if (m0 >= M) return;
    const int n0 = blockIdx.y * BN;

    const __half* A    = Ab    + (size_t)e * CAP * K;
    const float*  B    = Bb    + (size_t)e * N   * K;
    const float*  bias = biasb + (size_t)e * N;
    OutT*         C    = FUSE_OUT ? Cb : (Cb + (size_t)e * CAP * N);

    __shared__ __align__(16) __half As[2][BM][BKH];
    __shared__ __align__(16) __half Bs[2][BN][BKH];

    const int tid  = threadIdx.x;
    const int warp = tid >> 5, lane = tid & 31;
    const int wm   = warp >> 2;
    const int wn   = warp & 3;
    const int grp  = lane >> 2;
    const int tig  = lane & 3;

    const int arow = tid >> 3;
    const int aj   = (tid & 7) * 4;    // halves
    const int sk   = (tid & 7) * 4;    // floats

    const uint32_t sA = smem_u32(&As[0][0][0]);
    const uint32_t sB = smem_u32(&Bs[0][0][0]);
    const uint32_t ABUF = BM * BKH * 2, BBUF = BN * BKH * 2;
    const uint32_t aLane = (uint32_t)((wm * 64 + (lane & 15)) * (BKH * 2) + (lane >> 4) * 16);
    const uint32_t bLane = (uint32_t)((wn * 32 + ((lane >> 3) & 2) * 4 + (lane & 7)) * (BKH * 2)
                                      + ((lane >> 3) & 1) * 16);

    float acc[4][4][4];
    #pragma unroll
    for (int mi = 0; mi < 4; mi++)
        #pragma unroll
        for (int ni = 0; ni < 4; ni++)
            #pragma unroll
            for (int r = 0; r < 4; r++) acc[mi][ni][r] = 0.f;

    uint2  qa[4];
    float4 rb[4];
    const int T = K / BK;

    // prologue: LDG tile 0, STS into buf 0
    #pragma unroll
    for (int r = 0; r < 4; r++) {
        int gm = m0 + arow + r * 32;
        qa[r] = (gm < M) ? *(const uint2*)&A[(size_t)gm * K + aj] : make_uint2(0u, 0u);
        rb[r] = *(const float4*)&B[(size_t)(n0 + arow + r * 32) * K + sk];
    }
    #pragma unroll
    for (int r = 0; r < 4; r++) {
        *(uint2*)&As[0][arow + r * 32][aj] = qa[r];
        *(uint2*)&Bs[0][arow + r * 32][sk] =
            make_uint2(pack_h2(rb[r].x, rb[r].y), pack_h2(rb[r].z, rb[r].w));
    }
    __syncthreads();

    for (int t = 0; t < T; t++) {
        const int cur = t & 1, nxt = cur ^ 1;
        const bool more = (t + 1 < T);

        if (more) {
            const int kb = (t + 1) * BK;
            #pragma unroll
            for (int r = 0; r < 4; r++) {
                int gm = m0 + arow + r * 32;
                qa[r] = (gm < M) ? *(const uint2*)&A[(size_t)gm * K + kb + aj] : make_uint2(0u, 0u);
                rb[r] = *(const float4*)&B[(size_t)(n0 + arow + r * 32) * K + kb + sk];
            }
        }

        const uint32_t aB = sA + (uint32_t)cur * ABUF + aLane;
        const uint32_t bB = sB + (uint32_t)cur * BBUF + bLane;
        #pragma unroll
        for (int kk = 0; kk < BK; kk += 16) {
            const uint32_t ko = (uint32_t)kk * 2;
            uint32_t af[4][4], bq[2][4];
            #pragma unroll
            for (int mi = 0; mi < 4; mi++)
                ldm_x4(af[mi], aB + ko + (uint32_t)(mi * 16 * BKH * 2));
            #pragma unroll
            for (int p = 0; p < 2; p++)
                ldm_x4(bq[p], bB + ko + (uint32_t)(p * 16 * BKH * 2));
            #pragma unroll
            for (int mi = 0; mi < 4; mi++) {
                #pragma unroll
                for (int p = 0; p < 2; p++) {
                    mma_f16(acc[mi][2 * p + 0], af[mi], &bq[p][0]);
                    mma_f16(acc[mi][2 * p + 1], af[mi], &bq[p][2]);
                }
            }
        }

        if (more) {
            #pragma unroll
            for (int r = 0; r < 4; r++) {
                *(uint2*)&As[nxt][arow + r * 32][aj] = qa[r];
                *(uint2*)&Bs[nxt][arow + r * 32][sk] =
                    make_uint2(pack_h2(rb[r].x, rb[r].y), pack_h2(rb[r].z, rb[r].w));
            }
            __syncthreads();
        }
    }

    // epilogue
    if constexpr (FUSE_OUT) {
        // fused combine: out[token] += weight * (acc + bias), atomically
        #pragma unroll
        for (int mi = 0; mi < 4; mi++) {
            #pragma unroll
            for (int rr = 0; rr < 2; rr++) {
                int r = m0 + wm * 64 + mi * 16 + grp + rr * 8;
                if (r < M) {
                    int   tc  = g_slot_tok[e * CAP + r];
                    float wgt = g_tok_weight[tc];
                    float* orow = (float*)Cb + (size_t)(tc >> 1) * N;
                    #pragma unroll
                    for (int ni = 0; ni < 4; ni++) {
                        int col = n0 + wn * 32 + ni * 8 + tig * 2;
                        float2 bv = *(const float2*)&bias[col];
                        float a0 = acc[mi][ni][rr * 2 + 0] + bv.x;
                        float a1 = acc[mi][ni][rr * 2 + 1] + bv.y;
                        atomicAdd(&orow[col],     wgt * a0);
                        atomicAdd(&orow[col + 1], wgt * a1);
                    }
                }
            }
        }
    } else {
        #pragma unroll
        for (int mi = 0; mi < 4; mi++) {
            int r0 = m0 + wm * 64 + mi * 16 + grp;
            int r1 = r0 + 8;
            #pragma unroll
            for (int ni = 0; ni < 4; ni++) {
                int col = n0 + wn * 32 + ni * 8 + tig * 2;
                float2 bv = *(const float2*)&bias[col];
                if (r0 < M) {
                    float ox = acc[mi][ni][0] + bv.x, oy = acc[mi][ni][1] + bv.y;
                    if (RELU) { ox = fmaxf(ox, 0.f); oy = fmaxf(oy, 0.f); }
                    if constexpr (sizeof(OutT) == 2) {
                        *(uint32_t*)&C[(size_t)r0 * N + col] = pack_h2(ox, oy);
                    } else {
                        *(float2*)&C[(size_t)r0 * N + col] = make_float2(ox, oy);
                    }
                }
                if (r1 < M) {
                    float ox = acc[mi][ni][2] + bv.x, oy = acc[mi][ni][3] + bv.y;
                    if (RELU) { ox = fmaxf(ox, 0.f); oy = fmaxf(oy, 0.f); }
                    if constexpr (sizeof(OutT) == 2) {
                        *(uint32_t*)&C[(size_t)r1 * N + col] = pack_h2(ox, oy);
                    } else {
                        *(float2*)&C[(size_t)r1 * N + col] = make_float2(ox, oy);
                    }
                }
            }
        }
    }
}

// ---------------- device addresses + prewarm --------------------------------
// A __device__ symbol used by NAME in host code is the HOST shadow address;
// kernel parameters need the real device address via cudaGetSymbolAddress.
static __half* p_xg = nullptr;
static __half* p_h  = nullptr;
static float*  p_eo = nullptr;

static struct Prewarm {
    Prewarm() {
        (void)cudaGetSymbolAddress((void**)&p_xg, g_xg);
        (void)cudaGetSymbolAddress((void**)&p_h,  g_h);
        (void)cudaGetSymbolAddress((void**)&p_eo, g_eo);
        // prewarm every kernel pre-baseline (module load, lazy driver pools).
        zero_counts_kernel<<<1, 32>>>();
        routing_kernel<<<1, 256>>>(p_eo, p_eo, p_eo);
        dim3 g1(1, 1, 1);
        gemm_tc_kernel<true,  __half, false><<<g1, 256>>>(p_xg, p_eo, p_eo, p_h, D_MODEL, HIDDEN);
        gemm_tc_kernel<false, float,  true ><<<g1, 256>>>(p_h, p_eo, p_eo, p_eo, HIDDEN, D_MODEL);
        zero_counts_kernel<<<1, 32>>>();     // counts = 0 for launch #1
        (void)cudaDeviceSynchronize();
    }
} s_prewarm;

// ---------------- launch ----------------------------------------------------
extern "C" void kernel_launch(void* const* d_in, const int* in_sizes, int n_in,
                              void* d_out, int out_size) {
    const float* x      = (const float*)d_in[0];
    const float* gate_w = (const float*)d_in[1];
    const float* w1     = (const float*)d_in[2];
    const float* b1     = (const float*)d_in[3];
    const float* w2     = (const float*)d_in[4];
    const float* b2     = (const float*)d_in[5];
    float* out          = (float*)d_out;

    // counts start at 0 (prewarm seeds call #1; trailing reset covers replays)
    routing_kernel<<<T_TOK, 256>>>(x, gate_w, out);

    // fc1 + relu: [count x 1024](fp16) @ [4096 x 1024]^T -> [count x 4096](fp16)
    dim3 g1(CAP / BM, HIDDEN / BN, N_EXP);   // x = m-tile (16), y = n-tile (32)
    gemm_tc_kernel<true, __half, false><<<g1, 256>>>(p_xg, w1, b1, p_h, D_MODEL, HIDDEN);

    // fc2 fused with combine: atomicAdd weighted rows directly into out
    dim3 g2(CAP / BM, D_MODEL / BN, N_EXP);  // x = m-tile (16), y = n-tile (8)
    gemm_tc_kernel<false, float, true><<<g2, 256>>>(p_h, w2, b2, out, HIDDEN, D_MODEL);

    // reset counters for the next graph replay
    zero_counts_kernel<<<1, 32>>>();
}